// round 16
// baseline (speedup 1.0000x reference)
#include <cuda_runtime.h>
#include <math.h>

#define NPIX 4096
#define NNSZ (4096u*4096u)

// ------------------------- scratch (static device globals) -------------------------
__device__ float g_q[2*64*NPIX];        // q conv output
__device__ float g_y[2*512*NPIX];       // concat(out, context_flow)
__device__ float g_h[2*256*NPIX];       // conv1 output
__device__ float g_act1[2*512*NPIX];    // leaky(bn1(y))
__device__ float g_act2[2*256*NPIX];    // leaky(bn2(h))
__device__ float g_wpk1[4608*256];      // packed c1_w / sigma1   [k][oc]
__device__ float g_wpk2[2304*256];      // packed c2_w / sigma2
__device__ float g_wpk3[512*256];       // packed by_w / sigma3
__device__ float g_t[4608];
__device__ float g_s[256];
__device__ float g_sig[3];
__device__ float g_bn1a[512], g_bn1b[512];
__device__ float g_bn2a[256], g_bn2b[256];
__device__ float g_attn[2*NNSZ];        // fallback if attention not part of output

// ------------------------- spectral norm -------------------------
// t = W^T u   (W is [256][K] row-major, exactly the torch/jax reshape(h,-1))
__global__ void sn_vt(const float* __restrict__ w, const float* __restrict__ u, int K) {
    int k = blockIdx.x * 256 + threadIdx.x;
    if (k >= K) return;
    float acc = 0.f;
    #pragma unroll 4
    for (int oc = 0; oc < 256; ++oc) acc += w[oc * K + k] * u[oc];
    g_t[k] = acc;
}

// s[oc] = (W t)[oc] / (||t|| + eps)
__global__ void sn_sv(const float* __restrict__ w, int K) {
    int oc = blockIdx.x;
    int tid = threadIdx.x;
    __shared__ float red[256];
    float tsq = 0.f;
    for (int k = tid; k < K; k += 256) { float tv = g_t[k]; tsq += tv * tv; }
    red[tid] = tsq; __syncthreads();
    for (int o = 128; o > 0; o >>= 1) { if (tid < o) red[tid] += red[tid + o]; __syncthreads(); }
    float tnorm = sqrtf(red[0]) + 1e-12f;
    __syncthreads();
    float dot = 0.f;
    for (int k = tid; k < K; k += 256) dot += w[oc * K + k] * g_t[k];
    red[tid] = dot; __syncthreads();
    for (int o = 128; o > 0; o >>= 1) { if (tid < o) red[tid] += red[tid + o]; __syncthreads(); }
    if (tid == 0) g_s[oc] = red[0] / tnorm;
}

// sigma = (s.s) / (||s|| + eps)
__global__ void sn_sigma(int sel) {
    __shared__ float red[256];
    int tid = threadIdx.x;
    float v = g_s[tid];
    red[tid] = v * v; __syncthreads();
    for (int o = 128; o > 0; o >>= 1) { if (tid < o) red[tid] += red[tid + o]; __syncthreads(); }
    if (tid == 0) { float ssq = red[0]; g_sig[sel] = ssq / (sqrtf(ssq) + 1e-12f); }
}

// repack weights: wpk[(r*CIN+ic)*256 + oc] = w[oc][ic][r] / sigma
__global__ void pack_w(const float* __restrict__ w, int sel, int CIN, int TAPS) {
    int total = 256 * CIN * TAPS;
    int idx = blockIdx.x * 256 + threadIdx.x;
    if (idx >= total) return;
    float inv = 1.f / g_sig[sel];
    int oc = idx & 255;
    int kk = idx >> 8;
    int r = kk / CIN;
    int ic = kk - r * CIN;
    float* dst = (sel == 0) ? g_wpk1 : (sel == 1) ? g_wpk2 : g_wpk3;
    dst[idx] = w[(oc * CIN + ic) * TAPS + r] * inv;
}

// ------------------------- q = 1x1 conv (64 x 4096 = qw(64x256) @ x(256x4096)) -----
__global__ __launch_bounds__(256, 2) void qconv_kernel(
    const float* __restrict__ x, const float* __restrict__ qw) {
    __shared__ float As[8][68];    // [kk][cq]  (transposed weight tile)
    __shared__ float Bs[8][132];   // [kk][n]
    const int b = blockIdx.z;
    const int n0 = blockIdx.x * 128;
    const int tid = threadIdx.x;
    const int tx = tid & 15, ty = tid >> 4;
    const float* xb = x + (size_t)b * 256 * NPIX;

    const int lm = tid >> 3;     // 0..31 (A rows per elem)
    const int lk = tid & 7;
    const int bk0 = tid >> 7;    // 0..1
    const int bn = tid & 127;

    float areg[2], breg[4];
    float acc[4][8];
    #pragma unroll
    for (int i = 0; i < 4; i++)
        #pragma unroll
        for (int j = 0; j < 8; j++) acc[i][j] = 0.f;

    // prologue load k-step 0
    #pragma unroll
    for (int i = 0; i < 2; i++) areg[i] = qw[(lm + 32 * i) * 256 + lk];
    #pragma unroll
    for (int i = 0; i < 4; i++) breg[i] = xb[(size_t)(bk0 + 2 * i) * NPIX + n0 + bn];
    #pragma unroll
    for (int i = 0; i < 2; i++) As[lk][lm + 32 * i] = areg[i];
    #pragma unroll
    for (int i = 0; i < 4; i++) Bs[bk0 + 2 * i][bn] = breg[i];
    __syncthreads();

    const int STEPS = 32;  // K=256 / 8
    for (int s = 0; s < STEPS; ++s) {
        bool more = (s + 1 < STEPS);
        if (more) {
            int k0 = (s + 1) * 8;
            #pragma unroll
            for (int i = 0; i < 2; i++) areg[i] = qw[(lm + 32 * i) * 256 + k0 + lk];
            #pragma unroll
            for (int i = 0; i < 4; i++) breg[i] = xb[(size_t)(k0 + bk0 + 2 * i) * NPIX + n0 + bn];
        }
        #pragma unroll
        for (int kk = 0; kk < 8; kk++) {
            float4 a0 = *(const float4*)&As[kk][ty * 4];
            float4 b0 = *(const float4*)&Bs[kk][tx * 8];
            float4 b1 = *(const float4*)&Bs[kk][tx * 8 + 4];
            float af[4] = {a0.x, a0.y, a0.z, a0.w};
            float bf[8] = {b0.x, b0.y, b0.z, b0.w, b1.x, b1.y, b1.z, b1.w};
            #pragma unroll
            for (int i = 0; i < 4; i++)
                #pragma unroll
                for (int j = 0; j < 8; j++) acc[i][j] += af[i] * bf[j];
        }
        __syncthreads();
        if (more) {
            #pragma unroll
            for (int i = 0; i < 2; i++) As[lk][lm + 32 * i] = areg[i];
            #pragma unroll
            for (int i = 0; i < 4; i++) Bs[bk0 + 2 * i][bn] = breg[i];
            __syncthreads();
        }
    }
    #pragma unroll
    for (int i = 0; i < 4; i++) {
        int cq = ty * 4 + i;
        float* op = g_q + ((size_t)b * 64 + cq) * NPIX + n0 + tx * 8;
        #pragma unroll
        for (int j = 0; j < 8; j++) op[j] = acc[i][j];
    }
}

// ------------------------- energy = Q^T Q, tile 128(j) x 64(m), K=64 ---------------
__global__ __launch_bounds__(256, 2) void energy_gemm(float* attn_out) {
    float* attn = attn_out ? attn_out : g_attn;
    __shared__ float As[8][132];   // [kk][j]
    __shared__ float Bs[8][68];    // [kk][m]
    const int b = blockIdx.z;
    const int j0 = blockIdx.y * 128;
    const int m0 = blockIdx.x * 64;
    const int tid = threadIdx.x;
    const int tx = tid & 15, ty = tid >> 4;
    const float* qb = g_q + (size_t)b * 64 * NPIX;

    const int am = tid & 127, ak = tid >> 7;
    const int bn = tid & 63, bk = tid >> 6;

    float areg[4], breg[2];
    float acc[8][4];
    #pragma unroll
    for (int i = 0; i < 8; i++)
        #pragma unroll
        for (int j = 0; j < 4; j++) acc[i][j] = 0.f;

    #pragma unroll
    for (int i = 0; i < 4; i++) areg[i] = qb[(size_t)(ak + 2 * i) * NPIX + j0 + am];
    #pragma unroll
    for (int i = 0; i < 2; i++) breg[i] = qb[(size_t)(bk + 4 * i) * NPIX + m0 + bn];
    #pragma unroll
    for (int i = 0; i < 4; i++) As[ak + 2 * i][am] = areg[i];
    #pragma unroll
    for (int i = 0; i < 2; i++) Bs[bk + 4 * i][bn] = breg[i];
    __syncthreads();

    const int STEPS = 8;  // K=64
    for (int s = 0; s < STEPS; ++s) {
        bool more = (s + 1 < STEPS);
        if (more) {
            int k0 = (s + 1) * 8;
            #pragma unroll
            for (int i = 0; i < 4; i++) areg[i] = qb[(size_t)(k0 + ak + 2 * i) * NPIX + j0 + am];
            #pragma unroll
            for (int i = 0; i < 2; i++) breg[i] = qb[(size_t)(k0 + bk + 4 * i) * NPIX + m0 + bn];
        }
        #pragma unroll
        for (int kk = 0; kk < 8; kk++) {
            float4 a0 = *(const float4*)&As[kk][ty * 8];
            float4 a1 = *(const float4*)&As[kk][ty * 8 + 4];
            float4 b0 = *(const float4*)&Bs[kk][tx * 4];
            float af[8] = {a0.x, a0.y, a0.z, a0.w, a1.x, a1.y, a1.z, a1.w};
            float bf[4] = {b0.x, b0.y, b0.z, b0.w};
            #pragma unroll
            for (int i = 0; i < 8; i++)
                #pragma unroll
                for (int j = 0; j < 4; j++) acc[i][j] += af[i] * bf[j];
        }
        __syncthreads();
        if (more) {
            #pragma unroll
            for (int i = 0; i < 4; i++) As[ak + 2 * i][am] = areg[i];
            #pragma unroll
            for (int i = 0; i < 2; i++) Bs[bk + 4 * i][bn] = breg[i];
            __syncthreads();
        }
    }
    #pragma unroll
    for (int i = 0; i < 8; i++) {
        size_t row = (size_t)(j0 + ty * 8 + i);
        float* op = attn + (size_t)b * NNSZ + row * NPIX + m0 + tx * 4;
        #pragma unroll
        for (int j = 0; j < 4; j++) op[j] = acc[i][j];
    }
}

// ------------------------- row softmax (register-resident row) ---------------------
__global__ void softmax_rows(float* attn_out) {
    float* attn = attn_out ? attn_out : g_attn;
    const int b = blockIdx.y;
    const size_t row = blockIdx.x;
    float* p = attn + (size_t)b * NNSZ + row * NPIX;
    const int tid = threadIdx.x;
    float v[16];
    float mx = -1e30f;
    #pragma unroll
    for (int i = 0; i < 16; i++) { v[i] = p[tid + i * 256]; mx = fmaxf(mx, v[i]); }
    __shared__ float red[256];
    red[tid] = mx; __syncthreads();
    for (int o = 128; o > 0; o >>= 1) { if (tid < o) red[tid] = fmaxf(red[tid], red[tid + o]); __syncthreads(); }
    mx = red[0]; __syncthreads();
    float sum = 0.f;
    #pragma unroll
    for (int i = 0; i < 16; i++) { v[i] = __expf(v[i] - mx); sum += v[i]; }
    red[tid] = sum; __syncthreads();
    for (int o = 128; o > 0; o >>= 1) { if (tid < o) red[tid] += red[tid + o]; __syncthreads(); }
    float inv = 1.f / red[0];
    #pragma unroll
    for (int i = 0; i < 16; i++) p[tid + i * 256] = v[i] * inv;
}

// -------- value GEMM: y[c,j] = blend( sum_k V[c,k]*Attn[j,k] ), V = [x ; pre] ------
__global__ __launch_bounds__(256, 2) void value_gemm(
    const float* __restrict__ x, const float* __restrict__ pre,
    const float* __restrict__ mask, const float* attn_in,
    const float* __restrict__ gamma_p, const float* __restrict__ alpha_p) {
    const float* attn = attn_in ? attn_in : g_attn;
    __shared__ float As[8][132];   // [kk][c-tile]
    __shared__ float Bs[8][68];    // [kk][j-tile]
    const int b = blockIdx.z;
    const int m0 = blockIdx.y * 128;
    const int n0 = blockIdx.x * 64;
    const int tid = threadIdx.x;
    const int tx = tid & 15, ty = tid >> 4;
    const float* attnb = attn + (size_t)b * NNSZ;

    const int lm = tid >> 3;  // 0..31
    const int lk = tid & 7;
    const float* arow[4];
    #pragma unroll
    for (int i = 0; i < 4; i++) {
        int c = m0 + lm + 32 * i;
        arow[i] = (c < 256) ? (x + ((size_t)b * 256 + c) * NPIX)
                            : (pre + ((size_t)b * 256 + (c - 256)) * NPIX);
    }
    const float* brow[2];
    #pragma unroll
    for (int i = 0; i < 2; i++) brow[i] = attnb + (size_t)(n0 + lm + 32 * i) * NPIX;

    float areg[4], breg[2];
    float acc[8][4];
    #pragma unroll
    for (int i = 0; i < 8; i++)
        #pragma unroll
        for (int j = 0; j < 4; j++) acc[i][j] = 0.f;

    #pragma unroll
    for (int i = 0; i < 4; i++) areg[i] = arow[i][lk];
    #pragma unroll
    for (int i = 0; i < 2; i++) breg[i] = brow[i][lk];
    #pragma unroll
    for (int i = 0; i < 4; i++) As[lk][lm + 32 * i] = areg[i];
    #pragma unroll
    for (int i = 0; i < 2; i++) Bs[lk][lm + 32 * i] = breg[i];
    __syncthreads();

    const int STEPS = 512;  // K=4096
    for (int s = 0; s < STEPS; ++s) {
        bool more = (s + 1 < STEPS);
        if (more) {
            int k0 = (s + 1) * 8 + lk;
            #pragma unroll
            for (int i = 0; i < 4; i++) areg[i] = arow[i][k0];
            #pragma unroll
            for (int i = 0; i < 2; i++) breg[i] = brow[i][k0];
        }
        #pragma unroll
        for (int kk = 0; kk < 8; kk++) {
            float4 a0 = *(const float4*)&As[kk][ty * 8];
            float4 a1 = *(const float4*)&As[kk][ty * 8 + 4];
            float4 b0 = *(const float4*)&Bs[kk][tx * 4];
            float af[8] = {a0.x, a0.y, a0.z, a0.w, a1.x, a1.y, a1.z, a1.w};
            float bf[4] = {b0.x, b0.y, b0.z, b0.w};
            #pragma unroll
            for (int i = 0; i < 8; i++)
                #pragma unroll
                for (int j = 0; j < 4; j++) acc[i][j] += af[i] * bf[j];
        }
        __syncthreads();
        if (more) {
            #pragma unroll
            for (int i = 0; i < 4; i++) As[lk][lm + 32 * i] = areg[i];
            #pragma unroll
            for (int i = 0; i < 2; i++) Bs[lk][lm + 32 * i] = breg[i];
            __syncthreads();
        }
    }
    // epilogue: gamma/alpha/mask blend -> y
    const float ga = *gamma_p, al = *alpha_p;
    #pragma unroll
    for (int i = 0; i < 8; i++) {
        int c = m0 + ty * 8 + i;
        #pragma unroll
        for (int j = 0; j < 4; j++) {
            int col = n0 + tx * 4 + j;
            float a = acc[i][j], v;
            if (c < 256) {
                v = ga * a + x[((size_t)b * 256 + c) * NPIX + col];
            } else {
                float mk = mask[(size_t)b * NPIX + col];
                v = al * (1.f - mk) * a + mk * pre[((size_t)b * 256 + (c - 256)) * NPIX + col];
            }
            g_y[((size_t)b * 512 + c) * NPIX + col] = v;
        }
    }
}

// ------------------------- BN stats (per channel over B*H*W) -----------------------
__global__ void bn_stats(int sel, const float* __restrict__ scale, const float* __restrict__ bias) {
    const int C = sel ? 256 : 512;
    const float* in = sel ? g_h : g_y;
    float* aout = sel ? g_bn2a : g_bn1a;
    float* bout = sel ? g_bn2b : g_bn1b;
    const int ch = blockIdx.x;
    const int tid = threadIdx.x;
    __shared__ float rs[256], rq[256];
    float s = 0.f, q = 0.f;
    for (int b = 0; b < 2; b++) {
        const float* p = in + ((size_t)b * C + ch) * NPIX;
        for (int i = tid; i < NPIX; i += 256) { float v = p[i]; s += v; q += v * v; }
    }
    rs[tid] = s; rq[tid] = q; __syncthreads();
    for (int o = 128; o > 0; o >>= 1) {
        if (tid < o) { rs[tid] += rs[tid + o]; rq[tid] += rq[tid + o]; }
        __syncthreads();
    }
    if (tid == 0) {
        float mean = rs[0] / 8192.f;
        float var = rq[0] / 8192.f - mean * mean;
        float a = scale[ch] * rsqrtf(var + 1e-5f);
        aout[ch] = a;
        bout[ch] = bias[ch] - mean * a;
    }
}

// ------------------------- fused BN-apply + leaky ----------------------------------
__global__ void bn_act(int sel) {
    const int C = sel ? 256 : 512;
    const float* in = sel ? g_h : g_y;
    const float* a = sel ? g_bn2a : g_bn1a;
    const float* bb = sel ? g_bn2b : g_bn1b;
    float* o = sel ? g_act2 : g_act1;
    int idx = blockIdx.x * 256 + threadIdx.x;
    int ch = (idx >> 12) & (C - 1);
    float v = a[ch] * in[idx] + bb[ch];
    o[idx] = v > 0.f ? v : 0.01f * v;
}

// ---------- conv as implicit GEMM: out[oc,n] = sum_{r,ic} Wpk[k][oc]*in[ic,n+off] --
template<int CIN, int TAPS, bool ACC>
__global__ __launch_bounds__(256, 2) void conv_gemm(int sel, float* __restrict__ outp) {
    const float* wpk = (sel == 0) ? g_wpk1 : (sel == 1) ? g_wpk2 : g_wpk3;
    const float* in  = (sel == 0) ? g_act1 : (sel == 1) ? g_act2 : g_y;
    float* out = (sel == 0) ? g_h : outp;

    constexpr int K = CIN * TAPS;
    constexpr int STEPS = K / 8;
    __shared__ float As[8][132];   // [kk][oc-tile]
    __shared__ float Bs[8][68];    // [kk][n-tile]
    const int b = blockIdx.z;
    const int m0 = blockIdx.y * 128;
    const int n0 = blockIdx.x * 64;
    const int tid = threadIdx.x;
    const int tx = tid & 15, ty = tid >> 4;
    const float* inb = in + (size_t)b * CIN * NPIX;

    const int am = tid & 127, ak = tid >> 7;
    const int bn = tid & 63, bk = tid >> 6;
    const int ng = n0 + bn;
    const int px = ng & 63, py = ng >> 6;

    float areg[4], breg[2];
    float acc[8][4];
    #pragma unroll
    for (int i = 0; i < 8; i++)
        #pragma unroll
        for (int j = 0; j < 4; j++) acc[i][j] = 0.f;

    // --- load step s=0 ---
    {
        #pragma unroll
        for (int i = 0; i < 4; i++) areg[i] = wpk[(size_t)(ak + 2 * i) * 256 + m0 + am];
        #pragma unroll
        for (int i = 0; i < 2; i++) {
            int k = bk + 4 * i;
            if (TAPS == 1) {
                breg[i] = inb[(size_t)k * NPIX + ng];
            } else {
                int r = k / CIN, ic = k - r * CIN;
                int dy = r / 3 - 1, dx = r - (r / 3) * 3 - 1;
                bool ok = ((unsigned)(px + dx) < 64u) && ((unsigned)(py + dy) < 64u);
                breg[i] = ok ? inb[(size_t)ic * NPIX + ng + dy * 64 + dx] : 0.f;
            }
        }
    }
    #pragma unroll
    for (int i = 0; i < 4; i++) As[ak + 2 * i][am] = areg[i];
    #pragma unroll
    for (int i = 0; i < 2; i++) Bs[bk + 4 * i][bn] = breg[i];
    __syncthreads();

    for (int s = 0; s < STEPS; ++s) {
        bool more = (s + 1 < STEPS);
        if (more) {
            int k0 = (s + 1) * 8;
            #pragma unroll
            for (int i = 0; i < 4; i++) areg[i] = wpk[(size_t)(k0 + ak + 2 * i) * 256 + m0 + am];
            #pragma unroll
            for (int i = 0; i < 2; i++) {
                int k = k0 + bk + 4 * i;
                if (TAPS == 1) {
                    breg[i] = inb[(size_t)k * NPIX + ng];
                } else {
                    int r = k / CIN, ic = k - r * CIN;
                    int dy = r / 3 - 1, dx = r - (r / 3) * 3 - 1;
                    bool ok = ((unsigned)(px + dx) < 64u) && ((unsigned)(py + dy) < 64u);
                    breg[i] = ok ? inb[(size_t)ic * NPIX + ng + dy * 64 + dx] : 0.f;
                }
            }
        }
        #pragma unroll
        for (int kk = 0; kk < 8; kk++) {
            float4 a0 = *(const float4*)&As[kk][ty * 8];
            float4 a1 = *(const float4*)&As[kk][ty * 8 + 4];
            float4 b0 = *(const float4*)&Bs[kk][tx * 4];
            float af[8] = {a0.x, a0.y, a0.z, a0.w, a1.x, a1.y, a1.z, a1.w};
            float bf[4] = {b0.x, b0.y, b0.z, b0.w};
            #pragma unroll
            for (int i = 0; i < 8; i++)
                #pragma unroll
                for (int j = 0; j < 4; j++) acc[i][j] += af[i] * bf[j];
        }
        __syncthreads();
        if (more) {
            #pragma unroll
            for (int i = 0; i < 4; i++) As[ak + 2 * i][am] = areg[i];
            #pragma unroll
            for (int i = 0; i < 2; i++) Bs[bk + 4 * i][bn] = breg[i];
            __syncthreads();
        }
    }
    #pragma unroll
    for (int i = 0; i < 8; i++) {
        int oc = m0 + ty * 8 + i;
        float* op = out + ((size_t)b * 256 + oc) * NPIX + n0 + tx * 4;
        #pragma unroll
        for (int j = 0; j < 4; j++) {
            if (ACC) op[j] += acc[i][j];
            else     op[j] = acc[i][j];
        }
    }
}

// ----------------------------------- launch ----------------------------------------
extern "C" void kernel_launch(void* const* d_in, const int* in_sizes, int n_in,
                              void* d_out, int out_size) {
    const float* x     = (const float*)d_in[0];
    const float* pre   = (const float*)d_in[1];
    const float* mask  = (const float*)d_in[2];
    const float* q_w   = (const float*)d_in[3];
    const float* gamma = (const float*)d_in[4];
    const float* alpha = (const float*)d_in[5];
    const float* bn1_s = (const float*)d_in[6];
    const float* bn1_b = (const float*)d_in[7];
    const float* c1_w  = (const float*)d_in[8];
    const float* u1    = (const float*)d_in[9];
    const float* bn2_s = (const float*)d_in[11];
    const float* bn2_b = (const float*)d_in[12];
    const float* c2_w  = (const float*)d_in[13];
    const float* u2    = (const float*)d_in[14];
    const float* by_w  = (const float*)d_in[16];
    const float* u3    = (const float*)d_in[17];

    float* res = (float*)d_out;                       // [2,256,64,64]
    const long long full = (long long)2 * 256 * NPIX + (long long)2 * NNSZ;
    float* attnp = ((long long)out_size >= full) ? (res + 2 * 256 * NPIX) : nullptr;

    // --- spectral norm + weight repack (sigma folded in) ---
    const float* ws[3] = {c1_w, c2_w, by_w};
    const float* us[3] = {u1, u2, u3};
    const int cins[3] = {512, 256, 512};
    const int taps[3] = {9, 9, 1};
    for (int i = 0; i < 3; i++) {
        int K = cins[i] * taps[i];
        sn_vt<<<(K + 255) / 256, 256>>>(ws[i], us[i], K);
        sn_sv<<<256, 256>>>(ws[i], K);
        sn_sigma<<<1, 256>>>(i);
        pack_w<<<(256 * K + 255) / 256, 256>>>(ws[i], i, cins[i], taps[i]);
    }

    // --- attention path ---
    qconv_kernel<<<dim3(32, 1, 2), 256>>>(x, q_w);
    energy_gemm<<<dim3(64, 32, 2), 256>>>(attnp);
    softmax_rows<<<dim3(4096, 2), 256>>>(attnp);
    value_gemm<<<dim3(64, 4, 2), 256>>>(x, pre, mask, attnp, gamma, alpha);

    // --- ResBlock ---
    bn_stats<<<512, 256>>>(0, bn1_s, bn1_b);
    bn_act<<<(2 * 512 * NPIX) / 256, 256>>>(0);
    conv_gemm<512, 9, false><<<dim3(64, 2, 2), 256>>>(0, nullptr);   // conv1 -> g_h
    bn_stats<<<256, 256>>>(1, bn2_s, bn2_b);
    bn_act<<<(2 * 256 * NPIX) / 256, 256>>>(1);
    conv_gemm<512, 1, false><<<dim3(64, 2, 2), 256>>>(2, res);       // shortcut -> res
    conv_gemm<256, 9, true><<<dim3(64, 2, 2), 256>>>(1, res);        // conv2 += res
}

// round 17
// speedup vs baseline: 1.0049x; 1.0049x over previous
#include <cuda_runtime.h>
#include <math.h>

#define NPIX 4096
#define NNSZ (4096u*4096u)

// ------------------------- scratch (static device globals) -------------------------
__device__ float g_q[2*64*NPIX];        // q conv output
__device__ float g_y[2*512*NPIX];       // concat(out, context_flow)
__device__ float g_h[2*256*NPIX];       // conv1 output
__device__ float g_act1[2*512*NPIX];    // leaky(bn1(y))
__device__ float g_act2[2*256*NPIX];    // leaky(bn2(h))
__device__ float g_wpk1[4608*256];      // packed c1_w / sigma1   [k][oc]
__device__ float g_wpk2[2304*256];      // packed c2_w / sigma2
__device__ float g_wpk3[512*256];       // packed by_w / sigma3
__device__ float g_t[4608];
__device__ float g_s[256];
__device__ float g_sig[3];
__device__ float g_bn1a[512], g_bn1b[512];
__device__ float g_bn2a[256], g_bn2b[256];
__device__ float g_attn[2*NNSZ];        // fallback if attention not part of output

// ------------------------- spectral norm -------------------------
// t = W^T u   (W is [256][K] row-major, exactly the torch/jax reshape(h,-1))
__global__ void sn_vt(const float* __restrict__ w, const float* __restrict__ u, int K) {
    int k = blockIdx.x * 256 + threadIdx.x;
    if (k >= K) return;
    float acc = 0.f;
    #pragma unroll 4
    for (int oc = 0; oc < 256; ++oc) acc += w[oc * K + k] * u[oc];
    g_t[k] = acc;
}

// s[oc] = (W t)[oc] / (||t|| + eps)
__global__ void sn_sv(const float* __restrict__ w, int K) {
    int oc = blockIdx.x;
    int tid = threadIdx.x;
    __shared__ float red[256];
    float tsq = 0.f;
    for (int k = tid; k < K; k += 256) { float tv = g_t[k]; tsq += tv * tv; }
    red[tid] = tsq; __syncthreads();
    for (int o = 128; o > 0; o >>= 1) { if (tid < o) red[tid] += red[tid + o]; __syncthreads(); }
    float tnorm = sqrtf(red[0]) + 1e-12f;
    __syncthreads();
    float dot = 0.f;
    for (int k = tid; k < K; k += 256) dot += w[oc * K + k] * g_t[k];
    red[tid] = dot; __syncthreads();
    for (int o = 128; o > 0; o >>= 1) { if (tid < o) red[tid] += red[tid + o]; __syncthreads(); }
    if (tid == 0) g_s[oc] = red[0] / tnorm;
}

// sigma = (s.s) / (||s|| + eps)
__global__ void sn_sigma(int sel) {
    __shared__ float red[256];
    int tid = threadIdx.x;
    float v = g_s[tid];
    red[tid] = v * v; __syncthreads();
    for (int o = 128; o > 0; o >>= 1) { if (tid < o) red[tid] += red[tid + o]; __syncthreads(); }
    if (tid == 0) { float ssq = red[0]; g_sig[sel] = ssq / (sqrtf(ssq) + 1e-12f); }
}

// repack weights: wpk[(r*CIN+ic)*256 + oc] = w[oc][ic][r] / sigma
__global__ void pack_w(const float* __restrict__ w, int sel, int CIN, int TAPS) {
    int total = 256 * CIN * TAPS;
    int idx = blockIdx.x * 256 + threadIdx.x;
    if (idx >= total) return;
    float inv = 1.f / g_sig[sel];
    int oc = idx & 255;
    int kk = idx >> 8;
    int r = kk / CIN;
    int ic = kk - r * CIN;
    float* dst = (sel == 0) ? g_wpk1 : (sel == 1) ? g_wpk2 : g_wpk3;
    dst[idx] = w[(oc * CIN + ic) * TAPS + r] * inv;
}

// ------------------------- q = 1x1 conv (64 x 4096 = qw(64x256) @ x(256x4096)) -----
__global__ __launch_bounds__(256, 2) void qconv_kernel(
    const float* __restrict__ x, const float* __restrict__ qw) {
    __shared__ float As[8][68];    // [kk][cq]  (transposed weight tile)
    __shared__ float Bs[8][132];   // [kk][n]
    const int b = blockIdx.z;
    const int n0 = blockIdx.x * 128;
    const int tid = threadIdx.x;
    const int tx = tid & 15, ty = tid >> 4;
    const float* xb = x + (size_t)b * 256 * NPIX;

    const int lm = tid >> 3;     // 0..31 (A rows per elem)
    const int lk = tid & 7;
    const int bk0 = tid >> 7;    // 0..1
    const int bn = tid & 127;

    float areg[2], breg[4];
    float acc[4][8];
    #pragma unroll
    for (int i = 0; i < 4; i++)
        #pragma unroll
        for (int j = 0; j < 8; j++) acc[i][j] = 0.f;

    // prologue load k-step 0
    #pragma unroll
    for (int i = 0; i < 2; i++) areg[i] = qw[(lm + 32 * i) * 256 + lk];
    #pragma unroll
    for (int i = 0; i < 4; i++) breg[i] = xb[(size_t)(bk0 + 2 * i) * NPIX + n0 + bn];
    #pragma unroll
    for (int i = 0; i < 2; i++) As[lk][lm + 32 * i] = areg[i];
    #pragma unroll
    for (int i = 0; i < 4; i++) Bs[bk0 + 2 * i][bn] = breg[i];
    __syncthreads();

    const int STEPS = 32;  // K=256 / 8
    for (int s = 0; s < STEPS; ++s) {
        bool more = (s + 1 < STEPS);
        if (more) {
            int k0 = (s + 1) * 8;
            #pragma unroll
            for (int i = 0; i < 2; i++) areg[i] = qw[(lm + 32 * i) * 256 + k0 + lk];
            #pragma unroll
            for (int i = 0; i < 4; i++) breg[i] = xb[(size_t)(k0 + bk0 + 2 * i) * NPIX + n0 + bn];
        }
        #pragma unroll
        for (int kk = 0; kk < 8; kk++) {
            float4 a0 = *(const float4*)&As[kk][ty * 4];
            float4 b0 = *(const float4*)&Bs[kk][tx * 8];
            float4 b1 = *(const float4*)&Bs[kk][tx * 8 + 4];
            float af[4] = {a0.x, a0.y, a0.z, a0.w};
            float bf[8] = {b0.x, b0.y, b0.z, b0.w, b1.x, b1.y, b1.z, b1.w};
            #pragma unroll
            for (int i = 0; i < 4; i++)
                #pragma unroll
                for (int j = 0; j < 8; j++) acc[i][j] += af[i] * bf[j];
        }
        __syncthreads();
        if (more) {
            #pragma unroll
            for (int i = 0; i < 2; i++) As[lk][lm + 32 * i] = areg[i];
            #pragma unroll
            for (int i = 0; i < 4; i++) Bs[bk0 + 2 * i][bn] = breg[i];
            __syncthreads();
        }
    }
    #pragma unroll
    for (int i = 0; i < 4; i++) {
        int cq = ty * 4 + i;
        float* op = g_q + ((size_t)b * 64 + cq) * NPIX + n0 + tx * 8;
        #pragma unroll
        for (int j = 0; j < 8; j++) op[j] = acc[i][j];
    }
}

// ------------------------- energy = Q^T Q, tile 128(j) x 64(m), K=64 ---------------
__global__ __launch_bounds__(256, 2) void energy_gemm(float* attn_out) {
    float* attn = attn_out ? attn_out : g_attn;
    __shared__ float As[8][132];   // [kk][j]
    __shared__ float Bs[8][68];    // [kk][m]
    const int b = blockIdx.z;
    const int j0 = blockIdx.y * 128;
    const int m0 = blockIdx.x * 64;
    const int tid = threadIdx.x;
    const int tx = tid & 15, ty = tid >> 4;
    const float* qb = g_q + (size_t)b * 64 * NPIX;

    const int am = tid & 127, ak = tid >> 7;
    const int bn = tid & 63, bk = tid >> 6;

    float areg[4], breg[2];
    float acc[8][4];
    #pragma unroll
    for (int i = 0; i < 8; i++)
        #pragma unroll
        for (int j = 0; j < 4; j++) acc[i][j] = 0.f;

    #pragma unroll
    for (int i = 0; i < 4; i++) areg[i] = qb[(size_t)(ak + 2 * i) * NPIX + j0 + am];
    #pragma unroll
    for (int i = 0; i < 2; i++) breg[i] = qb[(size_t)(bk + 4 * i) * NPIX + m0 + bn];
    #pragma unroll
    for (int i = 0; i < 4; i++) As[ak + 2 * i][am] = areg[i];
    #pragma unroll
    for (int i = 0; i < 2; i++) Bs[bk + 4 * i][bn] = breg[i];
    __syncthreads();

    const int STEPS = 8;  // K=64
    for (int s = 0; s < STEPS; ++s) {
        bool more = (s + 1 < STEPS);
        if (more) {
            int k0 = (s + 1) * 8;
            #pragma unroll
            for (int i = 0; i < 4; i++) areg[i] = qb[(size_t)(k0 + ak + 2 * i) * NPIX + j0 + am];
            #pragma unroll
            for (int i = 0; i < 2; i++) breg[i] = qb[(size_t)(k0 + bk + 4 * i) * NPIX + m0 + bn];
        }
        #pragma unroll
        for (int kk = 0; kk < 8; kk++) {
            float4 a0 = *(const float4*)&As[kk][ty * 8];
            float4 a1 = *(const float4*)&As[kk][ty * 8 + 4];
            float4 b0 = *(const float4*)&Bs[kk][tx * 4];
            float af[8] = {a0.x, a0.y, a0.z, a0.w, a1.x, a1.y, a1.z, a1.w};
            float bf[4] = {b0.x, b0.y, b0.z, b0.w};
            #pragma unroll
            for (int i = 0; i < 8; i++)
                #pragma unroll
                for (int j = 0; j < 4; j++) acc[i][j] += af[i] * bf[j];
        }
        __syncthreads();
        if (more) {
            #pragma unroll
            for (int i = 0; i < 4; i++) As[ak + 2 * i][am] = areg[i];
            #pragma unroll
            for (int i = 0; i < 2; i++) Bs[bk + 4 * i][bn] = breg[i];
            __syncthreads();
        }
    }
    #pragma unroll
    for (int i = 0; i < 8; i++) {
        size_t row = (size_t)(j0 + ty * 8 + i);
        float* op = attn + (size_t)b * NNSZ + row * NPIX + m0 + tx * 4;
        #pragma unroll
        for (int j = 0; j < 4; j++) op[j] = acc[i][j];
    }
}

// ------------------------- row softmax (register-resident row) ---------------------
__global__ void softmax_rows(float* attn_out) {
    float* attn = attn_out ? attn_out : g_attn;
    const int b = blockIdx.y;
    const size_t row = blockIdx.x;
    float* p = attn + (size_t)b * NNSZ + row * NPIX;
    const int tid = threadIdx.x;
    float v[16];
    float mx = -1e30f;
    #pragma unroll
    for (int i = 0; i < 16; i++) { v[i] = p[tid + i * 256]; mx = fmaxf(mx, v[i]); }
    __shared__ float red[256];
    red[tid] = mx; __syncthreads();
    for (int o = 128; o > 0; o >>= 1) { if (tid < o) red[tid] = fmaxf(red[tid], red[tid + o]); __syncthreads(); }
    mx = red[0]; __syncthreads();
    float sum = 0.f;
    #pragma unroll
    for (int i = 0; i < 16; i++) { v[i] = __expf(v[i] - mx); sum += v[i]; }
    red[tid] = sum; __syncthreads();
    for (int o = 128; o > 0; o >>= 1) { if (tid < o) red[tid] += red[tid + o]; __syncthreads(); }
    float inv = 1.f / red[0];
    #pragma unroll
    for (int i = 0; i < 16; i++) p[tid + i * 256] = v[i] * inv;
}

// -------- value GEMM: y[c,j] = blend( sum_k V[c,k]*Attn[j,k] ), V = [x ; pre] ------
__global__ __launch_bounds__(256, 2) void value_gemm(
    const float* __restrict__ x, const float* __restrict__ pre,
    const float* __restrict__ mask, const float* attn_in,
    const float* __restrict__ gamma_p, const float* __restrict__ alpha_p) {
    const float* attn = attn_in ? attn_in : g_attn;
    __shared__ float As[8][132];   // [kk][c-tile]
    __shared__ float Bs[8][68];    // [kk][j-tile]
    const int b = blockIdx.z;
    const int m0 = blockIdx.y * 128;
    const int n0 = blockIdx.x * 64;
    const int tid = threadIdx.x;
    const int tx = tid & 15, ty = tid >> 4;
    const float* attnb = attn + (size_t)b * NNSZ;

    const int lm = tid >> 3;  // 0..31
    const int lk = tid & 7;
    const float* arow[4];
    #pragma unroll
    for (int i = 0; i < 4; i++) {
        int c = m0 + lm + 32 * i;
        arow[i] = (c < 256) ? (x + ((size_t)b * 256 + c) * NPIX)
                            : (pre + ((size_t)b * 256 + (c - 256)) * NPIX);
    }
    const float* brow[2];
    #pragma unroll
    for (int i = 0; i < 2; i++) brow[i] = attnb + (size_t)(n0 + lm + 32 * i) * NPIX;

    float areg[4], breg[2];
    float acc[8][4];
    #pragma unroll
    for (int i = 0; i < 8; i++)
        #pragma unroll
        for (int j = 0; j < 4; j++) acc[i][j] = 0.f;

    #pragma unroll
    for (int i = 0; i < 4; i++) areg[i] = arow[i][lk];
    #pragma unroll
    for (int i = 0; i < 2; i++) breg[i] = brow[i][lk];
    #pragma unroll
    for (int i = 0; i < 4; i++) As[lk][lm + 32 * i] = areg[i];
    #pragma unroll
    for (int i = 0; i < 2; i++) Bs[lk][lm + 32 * i] = breg[i];
    __syncthreads();

    const int STEPS = 512;  // K=4096
    for (int s = 0; s < STEPS; ++s) {
        bool more = (s + 1 < STEPS);
        if (more) {
            int k0 = (s + 1) * 8 + lk;
            #pragma unroll
            for (int i = 0; i < 4; i++) areg[i] = arow[i][k0];
            #pragma unroll
            for (int i = 0; i < 2; i++) breg[i] = brow[i][k0];
        }
        #pragma unroll
        for (int kk = 0; kk < 8; kk++) {
            float4 a0 = *(const float4*)&As[kk][ty * 8];
            float4 a1 = *(const float4*)&As[kk][ty * 8 + 4];
            float4 b0 = *(const float4*)&Bs[kk][tx * 4];
            float af[8] = {a0.x, a0.y, a0.z, a0.w, a1.x, a1.y, a1.z, a1.w};
            float bf[4] = {b0.x, b0.y, b0.z, b0.w};
            #pragma unroll
            for (int i = 0; i < 8; i++)
                #pragma unroll
                for (int j = 0; j < 4; j++) acc[i][j] += af[i] * bf[j];
        }
        __syncthreads();
        if (more) {
            #pragma unroll
            for (int i = 0; i < 4; i++) As[lk][lm + 32 * i] = areg[i];
            #pragma unroll
            for (int i = 0; i < 2; i++) Bs[lk][lm + 32 * i] = breg[i];
            __syncthreads();
        }
    }
    // epilogue: gamma/alpha/mask blend -> y
    const float ga = *gamma_p, al = *alpha_p;
    #pragma unroll
    for (int i = 0; i < 8; i++) {
        int c = m0 + ty * 8 + i;
        #pragma unroll
        for (int j = 0; j < 4; j++) {
            int col = n0 + tx * 4 + j;
            float a = acc[i][j], v;
            if (c < 256) {
                v = ga * a + x[((size_t)b * 256 + c) * NPIX + col];
            } else {
                float mk = mask[(size_t)b * NPIX + col];
                v = al * (1.f - mk) * a + mk * pre[((size_t)b * 256 + (c - 256)) * NPIX + col];
            }
            g_y[((size_t)b * 512 + c) * NPIX + col] = v;
        }
    }
}

// ------------------------- BN stats (per channel over B*H*W) -----------------------
__global__ void bn_stats(int sel, const float* __restrict__ scale, const float* __restrict__ bias) {
    const int C = sel ? 256 : 512;
    const float* in = sel ? g_h : g_y;
    float* aout = sel ? g_bn2a : g_bn1a;
    float* bout = sel ? g_bn2b : g_bn1b;
    const int ch = blockIdx.x;
    const int tid = threadIdx.x;
    __shared__ float rs[256], rq[256];
    float s = 0.f, q = 0.f;
    for (int b = 0; b < 2; b++) {
        const float* p = in + ((size_t)b * C + ch) * NPIX;
        for (int i = tid; i < NPIX; i += 256) { float v = p[i]; s += v; q += v * v; }
    }
    rs[tid] = s; rq[tid] = q; __syncthreads();
    for (int o = 128; o > 0; o >>= 1) {
        if (tid < o) { rs[tid] += rs[tid + o]; rq[tid] += rq[tid + o]; }
        __syncthreads();
    }
    if (tid == 0) {
        float mean = rs[0] / 8192.f;
        float var = rq[0] / 8192.f - mean * mean;
        float a = scale[ch] * rsqrtf(var + 1e-5f);
        aout[ch] = a;
        bout[ch] = bias[ch] - mean * a;
    }
}

// ------------------------- fused BN-apply + leaky ----------------------------------
__global__ void bn_act(int sel) {
    const int C = sel ? 256 : 512;
    const float* in = sel ? g_h : g_y;
    const float* a = sel ? g_bn2a : g_bn1a;
    const float* bb = sel ? g_bn2b : g_bn1b;
    float* o = sel ? g_act2 : g_act1;
    int idx = blockIdx.x * 256 + threadIdx.x;
    int ch = (idx >> 12) & (C - 1);
    float v = a[ch] * in[idx] + bb[ch];
    o[idx] = v > 0.f ? v : 0.01f * v;
}

// ---------- conv as implicit GEMM: out[oc,n] = sum_{r,ic} Wpk[k][oc]*in[ic,n+off] --
template<int CIN, int TAPS, bool ACC>
__global__ __launch_bounds__(256, 2) void conv_gemm(int sel, float* __restrict__ outp) {
    const float* wpk = (sel == 0) ? g_wpk1 : (sel == 1) ? g_wpk2 : g_wpk3;
    const float* in  = (sel == 0) ? g_act1 : (sel == 1) ? g_act2 : g_y;
    float* out = (sel == 0) ? g_h : outp;

    constexpr int K = CIN * TAPS;
    constexpr int STEPS = K / 8;
    __shared__ float As[8][132];   // [kk][oc-tile]
    __shared__ float Bs[8][68];    // [kk][n-tile]
    const int b = blockIdx.z;
    const int m0 = blockIdx.y * 128;
    const int n0 = blockIdx.x * 64;
    const int tid = threadIdx.x;
    const int tx = tid & 15, ty = tid >> 4;
    const float* inb = in + (size_t)b * CIN * NPIX;

    const int am = tid & 127, ak = tid >> 7;
    const int bn = tid & 63, bk = tid >> 6;
    const int ng = n0 + bn;
    const int px = ng & 63, py = ng >> 6;

    float areg[4], breg[2];
    float acc[8][4];
    #pragma unroll
    for (int i = 0; i < 8; i++)
        #pragma unroll
        for (int j = 0; j < 4; j++) acc[i][j] = 0.f;

    // --- load step s=0 ---
    {
        #pragma unroll
        for (int i = 0; i < 4; i++) areg[i] = wpk[(size_t)(ak + 2 * i) * 256 + m0 + am];
        #pragma unroll
        for (int i = 0; i < 2; i++) {
            int k = bk + 4 * i;
            if (TAPS == 1) {
                breg[i] = inb[(size_t)k * NPIX + ng];
            } else {
                int r = k / CIN, ic = k - r * CIN;
                int dy = r / 3 - 1, dx = r - (r / 3) * 3 - 1;
                bool ok = ((unsigned)(px + dx) < 64u) && ((unsigned)(py + dy) < 64u);
                breg[i] = ok ? inb[(size_t)ic * NPIX + ng + dy * 64 + dx] : 0.f;
            }
        }
    }
    #pragma unroll
    for (int i = 0; i < 4; i++) As[ak + 2 * i][am] = areg[i];
    #pragma unroll
    for (int i = 0; i < 2; i++) Bs[bk + 4 * i][bn] = breg[i];
    __syncthreads();

    for (int s = 0; s < STEPS; ++s) {
        bool more = (s + 1 < STEPS);
        if (more) {
            int k0 = (s + 1) * 8;
            #pragma unroll
            for (int i = 0; i < 4; i++) areg[i] = wpk[(size_t)(k0 + ak + 2 * i) * 256 + m0 + am];
            #pragma unroll
            for (int i = 0; i < 2; i++) {
                int k = k0 + bk + 4 * i;
                if (TAPS == 1) {
                    breg[i] = inb[(size_t)k * NPIX + ng];
                } else {
                    int r = k / CIN, ic = k - r * CIN;
                    int dy = r / 3 - 1, dx = r - (r / 3) * 3 - 1;
                    bool ok = ((unsigned)(px + dx) < 64u) && ((unsigned)(py + dy) < 64u);
                    breg[i] = ok ? inb[(size_t)ic * NPIX + ng + dy * 64 + dx] : 0.f;
                }
            }
        }
        #pragma unroll
        for (int kk = 0; kk < 8; kk++) {
            float4 a0 = *(const float4*)&As[kk][ty * 8];
            float4 a1 = *(const float4*)&As[kk][ty * 8 + 4];
            float4 b0 = *(const float4*)&Bs[kk][tx * 4];
            float af[8] = {a0.x, a0.y, a0.z, a0.w, a1.x, a1.y, a1.z, a1.w};
            float bf[4] = {b0.x, b0.y, b0.z, b0.w};
            #pragma unroll
            for (int i = 0; i < 8; i++)
                #pragma unroll
                for (int j = 0; j < 4; j++) acc[i][j] += af[i] * bf[j];
        }
        __syncthreads();
        if (more) {
            #pragma unroll
            for (int i = 0; i < 4; i++) As[ak + 2 * i][am] = areg[i];
            #pragma unroll
            for (int i = 0; i < 2; i++) Bs[bk + 4 * i][bn] = breg[i];
            __syncthreads();
        }
    }
    #pragma unroll
    for (int i = 0; i < 8; i++) {
        int oc = m0 + ty * 8 + i;
        float* op = out + ((size_t)b * 256 + oc) * NPIX + n0 + tx * 4;
        #pragma unroll
        for (int j = 0; j < 4; j++) {
            if (ACC) op[j] += acc[i][j];
            else     op[j] = acc[i][j];
        }
    }
}

// ----------------------------------- launch ----------------------------------------
extern "C" void kernel_launch(void* const* d_in, const int* in_sizes, int n_in,
                              void* d_out, int out_size) {
    const float* x     = (const float*)d_in[0];
    const float* pre   = (const float*)d_in[1];
    const float* mask  = (const float*)d_in[2];
    const float* q_w   = (const float*)d_in[3];
    const float* gamma = (const float*)d_in[4];
    const float* alpha = (const float*)d_in[5];
    const float* bn1_s = (const float*)d_in[6];
    const float* bn1_b = (const float*)d_in[7];
    const float* c1_w  = (const float*)d_in[8];
    const float* u1    = (const float*)d_in[9];
    const float* bn2_s = (const float*)d_in[11];
    const float* bn2_b = (const float*)d_in[12];
    const float* c2_w  = (const float*)d_in[13];
    const float* u2    = (const float*)d_in[14];
    const float* by_w  = (const float*)d_in[16];
    const float* u3    = (const float*)d_in[17];

    float* res = (float*)d_out;                       // [2,256,64,64]
    const long long full = (long long)2 * 256 * NPIX + (long long)2 * NNSZ;
    float* attnp = ((long long)out_size >= full) ? (res + 2 * 256 * NPIX) : nullptr;

    // --- spectral norm + weight repack (sigma folded in) ---
    const float* ws[3] = {c1_w, c2_w, by_w};
    const float* us[3] = {u1, u2, u3};
    const int cins[3] = {512, 256, 512};
    const int taps[3] = {9, 9, 1};
    for (int i = 0; i < 3; i++) {
        int K = cins[i] * taps[i];
        sn_vt<<<(K + 255) / 256, 256>>>(ws[i], us[i], K);
        sn_sv<<<256, 256>>>(ws[i], K);
        sn_sigma<<<1, 256>>>(i);
        pack_w<<<(256 * K + 255) / 256, 256>>>(ws[i], i, cins[i], taps[i]);
    }

    // --- attention path ---
    qconv_kernel<<<dim3(32, 1, 2), 256>>>(x, q_w);
    energy_gemm<<<dim3(64, 32, 2), 256>>>(attnp);
    softmax_rows<<<dim3(4096, 2), 256>>>(attnp);
    value_gemm<<<dim3(64, 4, 2), 256>>>(x, pre, mask, attnp, gamma, alpha);

    // --- ResBlock ---
    bn_stats<<<512, 256>>>(0, bn1_s, bn1_b);
    bn_act<<<(2 * 512 * NPIX) / 256, 256>>>(0);
    conv_gemm<512, 9, false><<<dim3(64, 2, 2), 256>>>(0, nullptr);   // conv1 -> g_h
    bn_stats<<<256, 256>>>(1, bn2_s, bn2_b);
    bn_act<<<(2 * 256 * NPIX) / 256, 256>>>(1);
    conv_gemm<512, 1, false><<<dim3(64, 2, 2), 256>>>(2, res);       // shortcut -> res
    conv_gemm<256, 9, true><<<dim3(64, 2, 2), 256>>>(1, res);        // conv2 += res
}